// round 3
// baseline (speedup 1.0000x reference)
#include <cuda_runtime.h>
#include <cuda_bf16.h>
#include <math.h>

// ---------------------------------------------------------------------------
// LINKX forward, fp32 with packed fma.rn.f32x2 GEMMs + heterogeneous-grid
// overlap of the edge scatter with the x-branch GEMM.
//
// Launch sequence (default stream, graph-capturable):
//   zero     : g_agg = 0, g_deg = 0
//   mega1    : blocks [0,gb)    -> G1: g_hid  = relu(x @ wx1 + bx1)   (K=256)
//              blocks [gb,+S)   -> scatter: g_agg[dst] += emb[src], deg++
//   finalize : g_agg /= max(deg,1)
//   mega2    : blocks [0,gb)    -> G2: cat[:,0:128]   = g_hid  @ wx2 + bx2
//              blocks [gb,2gb)  -> G3: g_hid2 = relu(g_agg @ wa1 + ba1)
//   G4       : cat[:,128:256] = g_hid2 @ wa2 + ba2
//   G5       : g_hid = relu(relu(cat @ ww1 + bw1) + hx + ha)   (K=256)
//   G6       : out = g_hid @ wc + bc   (N=40)
// ---------------------------------------------------------------------------

#define NMAX   100000
#define HID    128
#define INDIM  256

typedef unsigned long long u64;

// Scratch (device globals: sanctioned no-alloc workaround)
__device__ float g_agg[(size_t)NMAX * HID];
__device__ float g_deg[NMAX];
__device__ float g_hid[(size_t)NMAX * HID];
__device__ float g_hid2[(size_t)NMAX * HID];
__device__ float g_cat[(size_t)NMAX * 2 * HID];

// ---- packed fp32 helpers ---------------------------------------------------
#define FMA2(d, a, b, c) \
    asm("fma.rn.f32x2 %0, %1, %2, %3;" : "=l"(d) : "l"(a), "l"(b), "l"(c))
#define PACK_DUP(d, x) \
    asm("mov.b64 %0, {%1, %1};" : "=l"(d) : "f"(x))
#define UNPACK2(lo, hi, v) \
    asm("mov.b64 {%0, %1}, %2;" : "=f"(lo), "=f"(hi) : "l"(v))

// ---------------------------------------------------------------------------
__global__ void zero_kernel(float4* agg4, float* deg, int n4, int nd) {
    int i = blockIdx.x * blockDim.x + threadIdx.x;
    if (i < n4) agg4[i] = make_float4(0.f, 0.f, 0.f, 0.f);
    if (i < nd) deg[i] = 0.f;
}

__global__ void finalize_kernel(float4* agg4, const float* __restrict__ deg, int M) {
    int i = blockIdx.x * blockDim.x + threadIdx.x;
    int total = M * (HID / 4);
    if (i >= total) return;
    int m = i >> 5;
    float inv = 1.0f / fmaxf(deg[m], 1.0f);
    float4 v = agg4[i];
    v.x *= inv; v.y *= inv; v.z *= inv; v.w *= inv;
    agg4[i] = v;
}

// ---------------------------------------------------------------------------
// Edge scatter body: one warp per edge, 32 lanes x float4 vector reduction.
__device__ __forceinline__ void scatter_body(const int* __restrict__ ei,
                                             const float* __restrict__ emb,
                                             float* __restrict__ agg,
                                             float* __restrict__ deg,
                                             int E, int sblk, int nsblk) {
    int warp  = ((sblk << 8) + threadIdx.x) >> 5;
    int lane  = threadIdx.x & 31;
    int nwarp = nsblk << 3;
    for (int e = warp; e < E; e += nwarp) {
        int src = __ldg(&ei[e]);
        int dst = __ldg(&ei[E + e]);
        float4 v = *(const float4*)(emb + (size_t)src * HID + lane * 4);
        atomicAdd((float4*)(agg + (size_t)dst * HID + lane * 4), v);
        if (lane == 0) atomicAdd(&deg[dst], 1.0f);
    }
}

// ---------------------------------------------------------------------------
// SGEMM body with f32x2 packed FMAs.
// C[blk 128 rows, 128 cols] = epi(A @ W + bias); tile 128x128, TK=16,
// 256 threads, 8x8 per thread (accumulated as 4 row-pairs x 8 cols in f32x2).
// EPI: 0 none, 1 relu, 2 LINKX combine (A must be g_cat, ld 256)
// ---------------------------------------------------------------------------
template <int K_DIM, int EPI>
__device__ __forceinline__ void gemm_body(const float* __restrict__ A,
                                          const float* __restrict__ W,
                                          const float* __restrict__ bias,
                                          float* __restrict__ C,
                                          int ldc, int coff, int M, int blk,
                                          float (*As)[128], float (*Bs)[128]) {
    const int tid = threadIdx.x;
    const int bm  = blk * 128;
    const int ty  = tid >> 4;
    const int tx  = tid & 15;
    const int rm  = ty * 8;
    const int cn  = tx * 8;

    u64 acc2[4][8];
#pragma unroll
    for (int i = 0; i < 4; ++i)
#pragma unroll
        for (int j = 0; j < 8; ++j) acc2[i][j] = 0ull;

    for (int k0 = 0; k0 < K_DIM; k0 += 16) {
        // A tile transposed into As[k][m]
#pragma unroll
        for (int u0 = 0; u0 < 512; u0 += 256) {
            int u   = u0 + tid;
            int row = u >> 2;
            int kq  = (u & 3) * 4;
            int gr  = bm + row;
            float4 v = make_float4(0.f, 0.f, 0.f, 0.f);
            if (gr < M) v = *(const float4*)&A[(size_t)gr * K_DIM + k0 + kq];
            As[kq + 0][row] = v.x;
            As[kq + 1][row] = v.y;
            As[kq + 2][row] = v.z;
            As[kq + 3][row] = v.w;
        }
        // B tile Bs[k][n]
#pragma unroll
        for (int u0 = 0; u0 < 512; u0 += 256) {
            int u  = u0 + tid;
            int kr = u >> 5;
            int nq = (u & 31) * 4;
            *(float4*)&Bs[kr][nq] = *(const float4*)&W[(size_t)(k0 + kr) * 128 + nq];
        }
        __syncthreads();

#pragma unroll
        for (int kk = 0; kk < 16; ++kk) {
            // a: 4 packed row-pairs (contiguous m in As -> natural f32x2)
            ulonglong2 av0 = *(const ulonglong2*)&As[kk][rm];
            ulonglong2 av1 = *(const ulonglong2*)&As[kk][rm + 4];
            u64 ap[4] = {av0.x, av0.y, av1.x, av1.y};
            // b: 8 scalars, each duplicated into an f32x2
            float4 b0 = *(const float4*)&Bs[kk][cn];
            float4 b1 = *(const float4*)&Bs[kk][cn + 4];
            float bs[8] = {b0.x, b0.y, b0.z, b0.w, b1.x, b1.y, b1.z, b1.w};
            u64 bd[8];
#pragma unroll
            for (int j = 0; j < 8; ++j) PACK_DUP(bd[j], bs[j]);
#pragma unroll
            for (int i = 0; i < 4; ++i)
#pragma unroll
                for (int j = 0; j < 8; ++j)
                    FMA2(acc2[i][j], ap[i], bd[j], acc2[i][j]);
        }
        __syncthreads();
    }

    float bb[8];
#pragma unroll
    for (int j = 0; j < 8; ++j) bb[j] = bias[cn + j];

#pragma unroll
    for (int i2 = 0; i2 < 4; ++i2) {
        float o0[8], o1[8];
#pragma unroll
        for (int j = 0; j < 8; ++j) {
            float lo, hi;
            UNPACK2(lo, hi, acc2[i2][j]);
            lo += bb[j]; hi += bb[j];
            if (EPI == 1) { lo = fmaxf(lo, 0.f); hi = fmaxf(hi, 0.f); }
            o0[j] = lo; o1[j] = hi;
        }
#pragma unroll
        for (int h = 0; h < 2; ++h) {
            int r = bm + rm + 2 * i2 + h;
            if (r >= M) continue;
            float* o = h ? o1 : o0;
            if (EPI == 2) {
                const float* row = &A[(size_t)r * 256];
                float4 hx0 = *(const float4*)&row[cn];
                float4 hx1 = *(const float4*)&row[cn + 4];
                float4 ha0 = *(const float4*)&row[128 + cn];
                float4 ha1 = *(const float4*)&row[128 + cn + 4];
                float hx[8] = {hx0.x, hx0.y, hx0.z, hx0.w, hx1.x, hx1.y, hx1.z, hx1.w};
                float ha[8] = {ha0.x, ha0.y, ha0.z, ha0.w, ha1.x, ha1.y, ha1.z, ha1.w};
#pragma unroll
                for (int j = 0; j < 8; ++j)
                    o[j] = fmaxf(fmaxf(o[j], 0.f) + hx[j] + ha[j], 0.f);
            }
            float* cp = &C[(size_t)r * ldc + coff + cn];
            *(float4*)(cp)     = make_float4(o[0], o[1], o[2], o[3]);
            *(float4*)(cp + 4) = make_float4(o[4], o[5], o[6], o[7]);
        }
    }
}

// ---------------------------------------------------------------------------
// mega1: G1 gemm (blocks < gb) + edge scatter (remaining blocks)
__global__ __launch_bounds__(256, 2)
void mega1_kernel(const float* __restrict__ x,
                  const float* __restrict__ wx1,
                  const float* __restrict__ bx1,
                  float* __restrict__ hid,
                  const int* __restrict__ ei,
                  const float* __restrict__ emb,
                  float* __restrict__ agg,
                  float* __restrict__ deg,
                  int M, int E, int gb, int nsblk) {
    __shared__ float As[16][128];
    __shared__ float Bs[16][128];
    if ((int)blockIdx.x < gb) {
        gemm_body<INDIM, 1>(x, wx1, bx1, hid, 128, 0, M, blockIdx.x, As, Bs);
    } else {
        scatter_body(ei, emb, agg, deg, E, blockIdx.x - gb, nsblk);
    }
}

// mega2: G2 (blocks < gb) + G3 (blocks >= gb)
__global__ __launch_bounds__(256, 2)
void mega2_kernel(const float* __restrict__ hid,
                  const float* __restrict__ wx2,
                  const float* __restrict__ bx2,
                  float* __restrict__ cat,
                  const float* __restrict__ agg,
                  const float* __restrict__ wa1,
                  const float* __restrict__ ba1,
                  float* __restrict__ hid2,
                  int M, int gb) {
    __shared__ float As[16][128];
    __shared__ float Bs[16][128];
    if ((int)blockIdx.x < gb) {
        gemm_body<HID, 0>(hid, wx2, bx2, cat, 256, 0, M, blockIdx.x, As, Bs);
    } else {
        gemm_body<HID, 1>(agg, wa1, ba1, hid2, 128, 0, M, blockIdx.x - gb, As, Bs);
    }
}

// plain single-GEMM kernel
template <int K_DIM, int EPI>
__global__ __launch_bounds__(256, 2)
void gemm_kernel(const float* __restrict__ A,
                 const float* __restrict__ W,
                 const float* __restrict__ bias,
                 float* __restrict__ C, int ldc, int coff, int M) {
    __shared__ float As[16][128];
    __shared__ float Bs[16][128];
    gemm_body<K_DIM, EPI>(A, W, bias, C, ldc, coff, M, blockIdx.x, As, Bs);
}

// ---------------------------------------------------------------------------
// Classifier: out[M,40] = A[M,128] @ W[128,40] + bias, f32x2 packed.
__global__ __launch_bounds__(128)
void gemm_out(const float* __restrict__ A,
              const float* __restrict__ W,
              const float* __restrict__ bias,
              float* __restrict__ out, int M) {
    __shared__ float As[16][128];
    __shared__ float Ws[16 * 40];

    const int tid = threadIdx.x;
    const int bm  = blockIdx.x * 128;
    const int ty  = tid >> 3;
    const int tx  = tid & 7;
    const int rm  = ty * 8;
    const int cn  = tx * 5;

    u64 acc2[4][5];
#pragma unroll
    for (int i = 0; i < 4; ++i)
#pragma unroll
        for (int j = 0; j < 5; ++j) acc2[i][j] = 0ull;

    for (int k0 = 0; k0 < 128; k0 += 16) {
#pragma unroll
        for (int u0 = 0; u0 < 512; u0 += 128) {
            int u   = u0 + tid;
            int row = u >> 2;
            int kq  = (u & 3) * 4;
            int gr  = bm + row;
            float4 v = make_float4(0.f, 0.f, 0.f, 0.f);
            if (gr < M) v = *(const float4*)&A[(size_t)gr * 128 + k0 + kq];
            As[kq + 0][row] = v.x;
            As[kq + 1][row] = v.y;
            As[kq + 2][row] = v.z;
            As[kq + 3][row] = v.w;
        }
        for (int u = tid; u < 16 * 40; u += 128) {
            int kr = u / 40, c = u % 40;
            Ws[u] = W[(size_t)(k0 + kr) * 40 + c];
        }
        __syncthreads();

#pragma unroll
        for (int kk = 0; kk < 16; ++kk) {
            ulonglong2 av0 = *(const ulonglong2*)&As[kk][rm];
            ulonglong2 av1 = *(const ulonglong2*)&As[kk][rm + 4];
            u64 ap[4] = {av0.x, av0.y, av1.x, av1.y};
            u64 wd[5];
#pragma unroll
            for (int j = 0; j < 5; ++j) PACK_DUP(wd[j], Ws[kk * 40 + cn + j]);
#pragma unroll
            for (int i = 0; i < 4; ++i)
#pragma unroll
                for (int j = 0; j < 5; ++j)
                    FMA2(acc2[i][j], ap[i], wd[j], acc2[i][j]);
        }
        __syncthreads();
    }

    float bb[5];
#pragma unroll
    for (int j = 0; j < 5; ++j) bb[j] = bias[cn + j];
#pragma unroll
    for (int i2 = 0; i2 < 4; ++i2) {
        float lo[5], hi[5];
#pragma unroll
        for (int j = 0; j < 5; ++j) UNPACK2(lo[j], hi[j], acc2[i2][j]);
        int r0 = bm + rm + 2 * i2;
        if (r0 < M)
#pragma unroll
            for (int j = 0; j < 5; ++j) out[(size_t)r0 * 40 + cn + j] = lo[j] + bb[j];
        if (r0 + 1 < M)
#pragma unroll
            for (int j = 0; j < 5; ++j) out[(size_t)(r0 + 1) * 40 + cn + j] = hi[j] + bb[j];
    }
}

// ---------------------------------------------------------------------------
extern "C" void kernel_launch(void* const* d_in, const int* in_sizes, int n_in,
                              void* d_out, int out_size) {
    const float* x   = (const float*)d_in[0];
    const int*   ei  = (const int*)  d_in[1];
    const float* emb = (const float*)d_in[2];
    const float* wx1 = (const float*)d_in[3];
    const float* bx1 = (const float*)d_in[4];
    const float* wx2 = (const float*)d_in[5];
    const float* bx2 = (const float*)d_in[6];
    const float* wa1 = (const float*)d_in[7];
    const float* ba1 = (const float*)d_in[8];
    const float* wa2 = (const float*)d_in[9];
    const float* ba2 = (const float*)d_in[10];
    const float* ww1 = (const float*)d_in[11];
    const float* bw1 = (const float*)d_in[12];
    const float* wc  = (const float*)d_in[13];
    const float* bc  = (const float*)d_in[14];
    float* out = (float*)d_out;

    const int M = in_sizes[0] / INDIM;   // 100000
    const int E = in_sizes[1] / 2;       // 1600000

    float *agg, *deg, *hid, *hid2, *cat;
    cudaGetSymbolAddress((void**)&agg,  g_agg);
    cudaGetSymbolAddress((void**)&deg,  g_deg);
    cudaGetSymbolAddress((void**)&hid,  g_hid);
    cudaGetSymbolAddress((void**)&hid2, g_hid2);
    cudaGetSymbolAddress((void**)&cat,  g_cat);

    const int n4 = M * (HID / 4);
    zero_kernel<<<(n4 + 255) / 256, 256>>>((float4*)agg, deg, n4, M);

    const int gb    = (M + 127) / 128;   // 782
    const int nsblk = 4096;              // scatter blocks (32768 warps)

    // G1 + scatter overlapped in one heterogeneous grid
    mega1_kernel<<<gb + nsblk, 256>>>(x, wx1, bx1, hid, ei, emb, agg, deg,
                                      M, E, gb, nsblk);
    finalize_kernel<<<(n4 + 255) / 256, 256>>>((float4*)agg, deg, M);

    // G2 (hid -> cat[:,0:128]) and G3 (agg -> hid2) are independent
    mega2_kernel<<<2 * gb, 256>>>(hid, wx2, bx2, cat, agg, wa1, ba1, hid2, M, gb);

    // G4: cat[:,128:256] = hid2 @ wa2 + ba2
    gemm_kernel<HID, 0><<<gb, 256>>>(hid2, wa2, ba2, cat, 256, 128, M);
    // G5: hid = relu(relu(cat @ ww1 + bw1) + hx + ha)
    gemm_kernel<2 * HID, 2><<<gb, 256>>>(cat, ww1, bw1, hid, 128, 0, M);
    // G6: classifier
    gemm_out<<<gb, 128>>>(hid, wc, bc, out, M);
}

// round 5
// speedup vs baseline: 1.6852x; 1.6852x over previous
#include <cuda_runtime.h>
#include <cuda_bf16.h>
#include <math.h>
#include <stdint.h>

// ---------------------------------------------------------------------------
// LINKX forward. G1..G5 via mma.sync bf16 (2-term bf16 split: hh+hl+lh) on
// the tensor pipe (legacy HMMA path — tcgen05 PTX not accepted at the
// harness's .target sm_103). Scatter/zero/finalize/classifier = R2 versions.
// ---------------------------------------------------------------------------

#define NMAX   100000
#define HID    128
#define INDIM  256

// Scratch (device globals: sanctioned no-alloc workaround)
__device__ float g_agg[(size_t)NMAX * HID];
__device__ float g_deg[NMAX];
__device__ float g_hid[(size_t)NMAX * HID];
__device__ float g_hid2[(size_t)NMAX * HID];
__device__ float g_cat[(size_t)NMAX * 2 * HID];
__device__ __align__(16) __nv_bfloat16 g_wt[229376];  // pre-split weights

// ---- tensor helpers -------------------------------------------------------
__device__ __forceinline__ uint32_t smem_u32(const void* p) {
    uint32_t a;
    asm("{ .reg .u64 t; cvta.to.shared.u64 t, %1; cvt.u32.u64 %0, t; }"
        : "=r"(a) : "l"(p));
    return a;
}

#define LDSM_X4(r0, r1, r2, r3, addr) \
    asm volatile("ldmatrix.sync.aligned.m8n8.x4.shared.b16 {%0,%1,%2,%3}, [%4];" \
                 : "=r"(r0), "=r"(r1), "=r"(r2), "=r"(r3) : "r"(addr))

#define MMA_BF16(acc, a, b0v, b1v) \
    asm volatile("mma.sync.aligned.m16n8k16.row.col.f32.bf16.bf16.f32 " \
                 "{%0,%1,%2,%3}, {%4,%5,%6,%7}, {%8,%9}, {%0,%1,%2,%3};" \
                 : "+f"((acc)[0]), "+f"((acc)[1]), "+f"((acc)[2]), "+f"((acc)[3]) \
                 : "r"((a)[0]), "r"((a)[1]), "r"((a)[2]), "r"((a)[3]), \
                   "r"(b0v), "r"(b1v))

__device__ __forceinline__ uint32_t pack_bf2(__nv_bfloat16 lo, __nv_bfloat16 hi) {
    __nv_bfloat162 p;
    p.x = lo; p.y = hi;
    return *reinterpret_cast<uint32_t*>(&p);
}

__device__ __forceinline__ void bsplit(float x, __nv_bfloat16& h, __nv_bfloat16& l) {
    h = __float2bfloat16(x);
    l = __float2bfloat16(x - __bfloat162float(h));
}

// ---------------------------------------------------------------------------
__global__ void zero_kernel(float4* agg4, float* deg, int n4, int nd) {
    int i = blockIdx.x * blockDim.x + threadIdx.x;
    if (i < n4) agg4[i] = make_float4(0.f, 0.f, 0.f, 0.f);
    if (i < nd) deg[i] = 0.f;
}

__global__ void scatter_kernel(const int* __restrict__ ei,
                               const float* __restrict__ emb,
                               float* __restrict__ agg,
                               float* __restrict__ deg,
                               int E) {
    int warp  = (blockIdx.x * blockDim.x + threadIdx.x) >> 5;
    int lane  = threadIdx.x & 31;
    int nwarp = (gridDim.x * blockDim.x) >> 5;
    for (int e = warp; e < E; e += nwarp) {
        int src = __ldg(&ei[e]);
        int dst = __ldg(&ei[E + e]);
        float4 v = *(const float4*)(emb + (size_t)src * HID + lane * 4);
        atomicAdd((float4*)(agg + (size_t)dst * HID + lane * 4), v);
        if (lane == 0) atomicAdd(&deg[dst], 1.0f);
    }
}

__global__ void finalize_kernel(float4* agg4, const float* __restrict__ deg, int M) {
    int i = blockIdx.x * blockDim.x + threadIdx.x;
    int total = M * (HID / 4);
    if (i >= total) return;
    int m = i >> 5;
    float inv = 1.0f / fmaxf(deg[m], 1.0f);
    float4 v = agg4[i];
    v.x *= inv; v.y *= inv; v.z *= inv; v.w *= inv;
    agg4[i] = v;
}

// W[K,128] fp32 -> WT: hi[128][K] bf16, then lo[128][K] bf16 (B^T layout)
__global__ void prep_wt(const float* __restrict__ W,
                        __nv_bfloat16* __restrict__ WT, int K) {
    int t = blockIdx.x * blockDim.x + threadIdx.x;
    if (t >= K * 128) return;
    int k = t >> 7, n = t & 127;
    __nv_bfloat16 h, l;
    bsplit(W[t], h, l);
    WT[(size_t)n * K + k] = h;
    WT[(size_t)128 * K + (size_t)n * K + k] = l;
}

// ---------------------------------------------------------------------------
// bf16-split tensor GEMM: C[128,128] tile = epi(A @ W + bias).
// smem tiles: 48-byte row stride (24 bf16) -> conflict-free ldmatrix.
// 8 warps: warp (wm = wid>>1, wn = wid&1) owns 32 rows x 64 cols.
// EPI: 0 none, 1 relu, 2 LINKX combine (A = g_cat, K_DIM = 256)
// ---------------------------------------------------------------------------
template <int K_DIM, int EPI>
__global__ __launch_bounds__(256, 2)
void mma_gemm(const float* __restrict__ A,
              const __nv_bfloat16* __restrict__ WT,
              const float* __restrict__ bias,
              float* __restrict__ C, int ldc, int coff, int M) {
    __shared__ __align__(16) __nv_bfloat16 AH[128 * 24];
    __shared__ __align__(16) __nv_bfloat16 AL[128 * 24];
    __shared__ __align__(16) __nv_bfloat16 BH[128 * 24];
    __shared__ __align__(16) __nv_bfloat16 BL[128 * 24];

    const int tid  = threadIdx.x;
    const int wid  = tid >> 5;
    const int lane = tid & 31;
    const int wm   = wid >> 1;       // 0..3: row group (32 rows)
    const int wn   = wid & 1;        // 0..1: col group (64 cols)
    const int bm   = blockIdx.x * 128;

    const uint32_t uAH = smem_u32(AH);
    const uint32_t uAL = smem_u32(AL);
    const uint32_t uBH = smem_u32(BH);
    const uint32_t uBL = smem_u32(BL);

    float acc[2][8][4];
#pragma unroll
    for (int i = 0; i < 2; ++i)
#pragma unroll
        for (int j = 0; j < 8; ++j)
#pragma unroll
            for (int q = 0; q < 4; ++q) acc[i][j][q] = 0.f;

    // ldmatrix addresses (fixed per thread)
    const int a_r0  = (lane & 7) + ((lane >> 3) & 1) * 8;  // row within 16
    const int a_ch  = lane >> 4;                            // k chunk
    const int b_n0  = (lane & 7) + ((lane >> 4) & 1) * 8;   // n within 16
    const int b_ch  = (lane >> 3) & 1;

    const int NC = K_DIM / 16;
    for (int c = 0; c < NC; ++c) {
        const int k0 = c * 16;
        // ---- stage A (convert + split) ----
        {
            int row = tid >> 1, h = tid & 1;
            int gr  = bm + row;
            float4 v0 = make_float4(0.f, 0.f, 0.f, 0.f), v1 = v0;
            if (gr < M) {
                const float* p = A + (size_t)gr * K_DIM + k0 + h * 8;
                v0 = *(const float4*)p;
                v1 = *(const float4*)(p + 4);
            }
            __nv_bfloat16 h0,h1,h2,h3,h4,h5,h6,h7, l0,l1,l2,l3,l4,l5,l6,l7;
            bsplit(v0.x, h0, l0); bsplit(v0.y, h1, l1);
            bsplit(v0.z, h2, l2); bsplit(v0.w, h3, l3);
            bsplit(v1.x, h4, l4); bsplit(v1.y, h5, l5);
            bsplit(v1.z, h6, l6); bsplit(v1.w, h7, l7);
            uint4 hv = make_uint4(pack_bf2(h0,h1), pack_bf2(h2,h3),
                                  pack_bf2(h4,h5), pack_bf2(h6,h7));
            uint4 lv = make_uint4(pack_bf2(l0,l1), pack_bf2(l2,l3),
                                  pack_bf2(l4,l5), pack_bf2(l6,l7));
            *(uint4*)&AH[row * 24 + h * 8] = hv;
            *(uint4*)&AL[row * 24 + h * 8] = lv;
        }
        // ---- stage B (pure copy from pre-split WT) ----
        {
            int n = tid >> 1, h = tid & 1;
            uint4 hv = *(const uint4*)&WT[(size_t)n * K_DIM + k0 + h * 8];
            uint4 lv = *(const uint4*)&WT[(size_t)128 * K_DIM + (size_t)n * K_DIM + k0 + h * 8];
            *(uint4*)&BH[n * 24 + h * 8] = hv;
            *(uint4*)&BL[n * 24 + h * 8] = lv;
        }
        __syncthreads();

        // ---- fragments + MMA ----
        uint32_t ah[2][4], al[2][4];
#pragma unroll
        for (int mt = 0; mt < 2; ++mt) {
            int arow = wm * 32 + mt * 16 + a_r0;
            LDSM_X4(ah[mt][0], ah[mt][1], ah[mt][2], ah[mt][3],
                    uAH + arow * 48 + a_ch * 16);
            LDSM_X4(al[mt][0], al[mt][1], al[mt][2], al[mt][3],
                    uAL + arow * 48 + a_ch * 16);
        }
#pragma unroll
        for (int np = 0; np < 4; ++np) {
            int bn = wn * 64 + np * 16 + b_n0;
            uint32_t bh[4], bl[4];
            LDSM_X4(bh[0], bh[1], bh[2], bh[3], uBH + bn * 48 + b_ch * 16);
            LDSM_X4(bl[0], bl[1], bl[2], bl[3], uBL + bn * 48 + b_ch * 16);
#pragma unroll
            for (int mt = 0; mt < 2; ++mt) {
#pragma unroll
                for (int t = 0; t < 2; ++t) {
                    float* a4 = acc[mt][np * 2 + t];
                    MMA_BF16(a4, ah[mt], bh[2 * t], bh[2 * t + 1]);   // hh
                    MMA_BF16(a4, ah[mt], bl[2 * t], bl[2 * t + 1]);   // hl
                    MMA_BF16(a4, al[mt], bh[2 * t], bh[2 * t + 1]);   // lh
                }
            }
        }
        __syncthreads();
    }

    // ---- epilogue ----
    const int lr = lane >> 2;
    const int lc = (lane & 3) * 2;
#pragma unroll
    for (int mt = 0; mt < 2; ++mt) {
#pragma unroll
        for (int g = 0; g < 8; ++g) {
            int col = wn * 64 + g * 8 + lc;
            float2 bv = *(const float2*)&bias[col];
#pragma unroll
            for (int half = 0; half < 2; ++half) {
                int r = bm + wm * 32 + mt * 16 + lr + half * 8;
                if (r >= M) continue;
                float z0 = acc[mt][g][2 * half + 0] + bv.x;
                float z1 = acc[mt][g][2 * half + 1] + bv.y;
                if (EPI == 1) { z0 = fmaxf(z0, 0.f); z1 = fmaxf(z1, 0.f); }
                if (EPI == 2) {
                    const float* rrow = A + (size_t)r * K_DIM;
                    float2 hx = *(const float2*)&rrow[col];
                    float2 ha = *(const float2*)&rrow[128 + col];
                    z0 = fmaxf(fmaxf(z0, 0.f) + hx.x + ha.x, 0.f);
                    z1 = fmaxf(fmaxf(z1, 0.f) + hx.y + ha.y, 0.f);
                }
                *(float2*)&C[(size_t)r * ldc + coff + col] = make_float2(z0, z1);
            }
        }
    }
}

// ---------------------------------------------------------------------------
// Classifier GEMM: out[M,40] = A[M,128] @ W[128,40] + bias (R2 SIMT version)
__global__ __launch_bounds__(128)
void gemm_out(const float* __restrict__ A,
              const float* __restrict__ W,
              const float* __restrict__ bias,
              float* __restrict__ out, int M) {
    __shared__ float As[16][128];
    __shared__ float Ws[16 * 40];

    const int tid = threadIdx.x;
    const int bm  = blockIdx.x * 128;
    const int ty  = tid >> 3;
    const int tx  = tid & 7;
    const int rm  = ty * 8;
    const int cn  = tx * 5;

    float acc[8][5];
#pragma unroll
    for (int i = 0; i < 8; ++i)
#pragma unroll
        for (int j = 0; j < 5; ++j) acc[i][j] = 0.f;

    for (int k0 = 0; k0 < 128; k0 += 16) {
#pragma unroll
        for (int u0 = 0; u0 < 512; u0 += 128) {
            int u   = u0 + tid;
            int row = u >> 2;
            int kq  = (u & 3) * 4;
            int gr  = bm + row;
            float4 v = make_float4(0.f, 0.f, 0.f, 0.f);
            if (gr < M) v = *(const float4*)&A[(size_t)gr * 128 + k0 + kq];
            As[kq + 0][row] = v.x;
            As[kq + 1][row] = v.y;
            As[kq + 2][row] = v.z;
            As[kq + 3][row] = v.w;
        }
        for (int u = tid; u < 16 * 40; u += 128) {
            int kr = u / 40, cc = u % 40;
            Ws[u] = W[(size_t)(k0 + kr) * 40 + cc];
        }
        __syncthreads();

#pragma unroll
        for (int kk = 0; kk < 16; ++kk) {
            float4 a0 = *(const float4*)&As[kk][rm];
            float4 a1 = *(const float4*)&As[kk][rm + 4];
            float a[8] = {a0.x, a0.y, a0.z, a0.w, a1.x, a1.y, a1.z, a1.w};
            float w[5];
#pragma unroll
            for (int j = 0; j < 5; ++j) w[j] = Ws[kk * 40 + cn + j];
#pragma unroll
            for (int i = 0; i < 8; ++i)
#pragma unroll
                for (int j = 0; j < 5; ++j)
                    acc[i][j] = fmaf(a[i], w[j], acc[i][j]);
        }
        __syncthreads();
    }

    float bb[5];
#pragma unroll
    for (int j = 0; j < 5; ++j) bb[j] = bias[cn + j];
#pragma unroll
    for (int i = 0; i < 8; ++i) {
        int r = bm + rm + i;
        if (r >= M) break;
#pragma unroll
        for (int j = 0; j < 5; ++j)
            out[(size_t)r * 40 + cn + j] = acc[i][j] + bb[j];
    }
}

// ---------------------------------------------------------------------------
extern "C" void kernel_launch(void* const* d_in, const int* in_sizes, int n_in,
                              void* d_out, int out_size) {
    const float* x   = (const float*)d_in[0];
    const int*   ei  = (const int*)  d_in[1];
    const float* emb = (const float*)d_in[2];
    const float* wx1 = (const float*)d_in[3];
    const float* bx1 = (const float*)d_in[4];
    const float* wx2 = (const float*)d_in[5];
    const float* bx2 = (const float*)d_in[6];
    const float* wa1 = (const float*)d_in[7];
    const float* ba1 = (const float*)d_in[8];
    const float* wa2 = (const float*)d_in[9];
    const float* ba2 = (const float*)d_in[10];
    const float* ww1 = (const float*)d_in[11];
    const float* bw1 = (const float*)d_in[12];
    const float* wc  = (const float*)d_in[13];
    const float* bc  = (const float*)d_in[14];
    float* out = (float*)d_out;

    const int M = in_sizes[0] / INDIM;   // 100000
    const int E = in_sizes[1] / 2;       // 1600000

    float *agg, *deg, *hid, *hid2, *cat;
    __nv_bfloat16* wt;
    cudaGetSymbolAddress((void**)&agg,  g_agg);
    cudaGetSymbolAddress((void**)&deg,  g_deg);
    cudaGetSymbolAddress((void**)&hid,  g_hid);
    cudaGetSymbolAddress((void**)&hid2, g_hid2);
    cudaGetSymbolAddress((void**)&cat,  g_cat);
    cudaGetSymbolAddress((void**)&wt,   g_wt);

    __nv_bfloat16* WT1 = wt;             // wx1 (K=256): 65536 elems
    __nv_bfloat16* WT2 = wt + 65536;     // wx2 (K=128): 32768
    __nv_bfloat16* WT3 = wt + 98304;     // wa1
    __nv_bfloat16* WT4 = wt + 131072;    // wa2
    __nv_bfloat16* WT5 = wt + 163840;    // ww1 (K=256): 65536

    const int n4 = M * (HID / 4);
    zero_kernel<<<(n4 + 255) / 256, 256>>>((float4*)agg, deg, n4, M);

    prep_wt<<<(256 * 128 + 255) / 256, 256>>>(wx1, WT1, 256);
    prep_wt<<<(128 * 128 + 255) / 256, 256>>>(wx2, WT2, 128);
    prep_wt<<<(128 * 128 + 255) / 256, 256>>>(wa1, WT3, 128);
    prep_wt<<<(128 * 128 + 255) / 256, 256>>>(wa2, WT4, 128);
    prep_wt<<<(256 * 128 + 255) / 256, 256>>>(ww1, WT5, 256);

    scatter_kernel<<<(E + 7) / 8, 256>>>(ei, emb, agg, deg, E);
    finalize_kernel<<<(n4 + 255) / 256, 256>>>((float4*)agg, deg, M);

    const int gb = (M + 127) / 128;   // 782
    // G1: hid = relu(x @ wx1 + bx1)
    mma_gemm<INDIM, 1><<<gb, 256>>>(x, WT1, bx1, hid, 128, 0, M);
    // G2: cat[:,0:128] = hid @ wx2 + bx2
    mma_gemm<HID, 0><<<gb, 256>>>(hid, WT2, bx2, cat, 256, 0, M);
    // G3: hid2 = relu(agg @ wa1 + ba1)
    mma_gemm<HID, 1><<<gb, 256>>>(agg, WT3, ba1, hid2, 128, 0, M);
    // G4: cat[:,128:256] = hid2 @ wa2 + ba2
    mma_gemm<HID, 0><<<gb, 256>>>(hid2, WT4, ba2, cat, 256, 128, M);
    // G5: hid = relu(relu(cat @ ww1 + bw1) + hx + ha)
    mma_gemm<2 * HID, 2><<<gb, 256>>>(cat, WT5, bw1, hid, 128, 0, M);
    // G6: classifier
    gemm_out<<<gb, 128>>>(hid, wc, bc, out, M);
}

// round 6
// speedup vs baseline: 1.7342x; 1.0291x over previous
#include <cuda_runtime.h>
#include <cuda_bf16.h>
#include <math.h>
#include <stdint.h>

// ---------------------------------------------------------------------------
// LINKX forward. G1..G5 via mma.sync bf16 (2-term split: hh+hl+lh) on the
// tensor pipe. Edge-scatter chain overlapped with the x-branch GEMMs via a
// side stream (capture fork/join). Single merged weight-prep kernel.
// ---------------------------------------------------------------------------

#define NMAX   100000
#define HID    128
#define INDIM  256

__device__ float g_agg[(size_t)NMAX * HID];
__device__ float g_deg[NMAX];
__device__ float g_hid[(size_t)NMAX * HID];
__device__ float g_hid2[(size_t)NMAX * HID];
__device__ float g_cat[(size_t)NMAX * 2 * HID];
__device__ __align__(16) __nv_bfloat16 g_wt[229376];

// ---- tensor helpers -------------------------------------------------------
__device__ __forceinline__ uint32_t smem_u32(const void* p) {
    uint32_t a;
    asm("{ .reg .u64 t; cvta.to.shared.u64 t, %1; cvt.u32.u64 %0, t; }"
        : "=r"(a) : "l"(p));
    return a;
}

#define LDSM_X4(r0, r1, r2, r3, addr) \
    asm volatile("ldmatrix.sync.aligned.m8n8.x4.shared.b16 {%0,%1,%2,%3}, [%4];" \
                 : "=r"(r0), "=r"(r1), "=r"(r2), "=r"(r3) : "r"(addr))

#define MMA_BF16(acc, a, b0v, b1v) \
    asm volatile("mma.sync.aligned.m16n8k16.row.col.f32.bf16.bf16.f32 " \
                 "{%0,%1,%2,%3}, {%4,%5,%6,%7}, {%8,%9}, {%0,%1,%2,%3};" \
                 : "+f"((acc)[0]), "+f"((acc)[1]), "+f"((acc)[2]), "+f"((acc)[3]) \
                 : "r"((a)[0]), "r"((a)[1]), "r"((a)[2]), "r"((a)[3]), \
                   "r"(b0v), "r"(b1v))

__device__ __forceinline__ uint32_t pack_bf2(__nv_bfloat16 lo, __nv_bfloat16 hi) {
    __nv_bfloat162 p;
    p.x = lo; p.y = hi;
    return *reinterpret_cast<uint32_t*>(&p);
}

__device__ __forceinline__ void bsplit(float x, __nv_bfloat16& h, __nv_bfloat16& l) {
    h = __float2bfloat16(x);
    l = __float2bfloat16(x - __bfloat162float(h));
}

// ---------------------------------------------------------------------------
__global__ void zero_kernel(float4* agg4, float* deg, int n4, int nd) {
    int i = blockIdx.x * blockDim.x + threadIdx.x;
    if (i < n4) agg4[i] = make_float4(0.f, 0.f, 0.f, 0.f);
    if (i < nd) deg[i] = 0.f;
}

__global__ void scatter_kernel(const int* __restrict__ ei,
                               const float* __restrict__ emb,
                               float* __restrict__ agg,
                               float* __restrict__ deg,
                               int E) {
    int warp  = (blockIdx.x * blockDim.x + threadIdx.x) >> 5;
    int lane  = threadIdx.x & 31;
    int nwarp = (gridDim.x * blockDim.x) >> 5;
    for (int e = warp; e < E; e += nwarp) {
        int src = __ldg(&ei[e]);
        int dst = __ldg(&ei[E + e]);
        float4 v = *(const float4*)(emb + (size_t)src * HID + lane * 4);
        atomicAdd((float4*)(agg + (size_t)dst * HID + lane * 4), v);
        if (lane == 0) atomicAdd(&deg[dst], 1.0f);
    }
}

__global__ void finalize_kernel(float4* agg4, const float* __restrict__ deg, int M) {
    int i = blockIdx.x * blockDim.x + threadIdx.x;
    int total = M * (HID / 4);
    if (i >= total) return;
    int m = i >> 5;
    float inv = 1.0f / fmaxf(deg[m], 1.0f);
    float4 v = agg4[i];
    v.x *= inv; v.y *= inv; v.z *= inv; v.w *= inv;
    agg4[i] = v;
}

// Merged weight prep: 5 matrices in one launch.
// Layout per matrix in WT: hi[128][K] then lo[128][K], B^T layout.
__global__ void prep_all(const float* __restrict__ wx1, const float* __restrict__ wx2,
                         const float* __restrict__ wa1, const float* __restrict__ wa2,
                         const float* __restrict__ ww1, __nv_bfloat16* __restrict__ WT) {
    // element space: [0,32768) wx1 | [32768,49152) wx2 | .. wa1 | .. wa2 | ww1
    int t = blockIdx.x * blockDim.x + threadIdx.x;
    const float* W;
    __nv_bfloat16* D;
    int K, base;
    if (t < 32768)      { W = wx1; D = WT;          K = 256; base = 0; }
    else if (t < 49152) { W = wx2; D = WT + 65536;  K = 128; base = 32768; }
    else if (t < 65536) { W = wa1; D = WT + 98304;  K = 128; base = 49152; }
    else if (t < 81920) { W = wa2; D = WT + 131072; K = 128; base = 65536; }
    else if (t < 114688){ W = ww1; D = WT + 163840; K = 256; base = 81920; }
    else return;
    int u = t - base;
    int k = u >> 7, n = u & 127;
    __nv_bfloat16 h, l;
    bsplit(W[u], h, l);
    D[(size_t)n * K + k] = h;
    D[(size_t)128 * K + (size_t)n * K + k] = l;
}

// ---------------------------------------------------------------------------
// bf16-split tensor GEMM (R5, known good): C[128,128] tile = epi(A@W + bias).
template <int K_DIM, int EPI>
__global__ __launch_bounds__(256, 2)
void mma_gemm(const float* __restrict__ A,
              const __nv_bfloat16* __restrict__ WT,
              const float* __restrict__ bias,
              float* __restrict__ C, int ldc, int coff, int M) {
    __shared__ __align__(16) __nv_bfloat16 AH[128 * 24];
    __shared__ __align__(16) __nv_bfloat16 AL[128 * 24];
    __shared__ __align__(16) __nv_bfloat16 BH[128 * 24];
    __shared__ __align__(16) __nv_bfloat16 BL[128 * 24];

    const int tid  = threadIdx.x;
    const int wid  = tid >> 5;
    const int lane = tid & 31;
    const int wm   = wid >> 1;
    const int wn   = wid & 1;
    const int bm   = blockIdx.x * 128;

    const uint32_t uAH = smem_u32(AH);
    const uint32_t uAL = smem_u32(AL);
    const uint32_t uBH = smem_u32(BH);
    const uint32_t uBL = smem_u32(BL);

    float acc[2][8][4];
#pragma unroll
    for (int i = 0; i < 2; ++i)
#pragma unroll
        for (int j = 0; j < 8; ++j)
#pragma unroll
            for (int q = 0; q < 4; ++q) acc[i][j][q] = 0.f;

    const int a_r0 = (lane & 7) + ((lane >> 3) & 1) * 8;
    const int a_ch = lane >> 4;
    const int b_n0 = (lane & 7) + ((lane >> 4) & 1) * 8;
    const int b_ch = (lane >> 3) & 1;

    const int NC = K_DIM / 16;
    for (int c = 0; c < NC; ++c) {
        const int k0 = c * 16;
        {
            int row = tid >> 1, h = tid & 1;
            int gr  = bm + row;
            float4 v0 = make_float4(0.f, 0.f, 0.f, 0.f), v1 = v0;
            if (gr < M) {
                const float* p = A + (size_t)gr * K_DIM + k0 + h * 8;
                v0 = *(const float4*)p;
                v1 = *(const float4*)(p + 4);
            }
            __nv_bfloat16 h0,h1,h2,h3,h4,h5,h6,h7, l0,l1,l2,l3,l4,l5,l6,l7;
            bsplit(v0.x, h0, l0); bsplit(v0.y, h1, l1);
            bsplit(v0.z, h2, l2); bsplit(v0.w, h3, l3);
            bsplit(v1.x, h4, l4); bsplit(v1.y, h5, l5);
            bsplit(v1.z, h6, l6); bsplit(v1.w, h7, l7);
            uint4 hv = make_uint4(pack_bf2(h0,h1), pack_bf2(h2,h3),
                                  pack_bf2(h4,h5), pack_bf2(h6,h7));
            uint4 lv = make_uint4(pack_bf2(l0,l1), pack_bf2(l2,l3),
                                  pack_bf2(l4,l5), pack_bf2(l6,l7));
            *(uint4*)&AH[row * 24 + h * 8] = hv;
            *(uint4*)&AL[row * 24 + h * 8] = lv;
        }
        {
            int n = tid >> 1, h = tid & 1;
            uint4 hv = *(const uint4*)&WT[(size_t)n * K_DIM + k0 + h * 8];
            uint4 lv = *(const uint4*)&WT[(size_t)128 * K_DIM + (size_t)n * K_DIM + k0 + h * 8];
            *(uint4*)&BH[n * 24 + h * 8] = hv;
            *(uint4*)&BL[n * 24 + h * 8] = lv;
        }
        __syncthreads();

        uint32_t ah[2][4], al[2][4];
#pragma unroll
        for (int mt = 0; mt < 2; ++mt) {
            int arow = wm * 32 + mt * 16 + a_r0;
            LDSM_X4(ah[mt][0], ah[mt][1], ah[mt][2], ah[mt][3],
                    uAH + arow * 48 + a_ch * 16);
            LDSM_X4(al[mt][0], al[mt][1], al[mt][2], al[mt][3],
                    uAL + arow * 48 + a_ch * 16);
        }
#pragma unroll
        for (int np = 0; np < 4; ++np) {
            int bn = wn * 64 + np * 16 + b_n0;
            uint32_t bh[4], bl[4];
            LDSM_X4(bh[0], bh[1], bh[2], bh[3], uBH + bn * 48 + b_ch * 16);
            LDSM_X4(bl[0], bl[1], bl[2], bl[3], uBL + bn * 48 + b_ch * 16);
#pragma unroll
            for (int mt = 0; mt < 2; ++mt) {
#pragma unroll
                for (int t = 0; t < 2; ++t) {
                    float* a4 = acc[mt][np * 2 + t];
                    MMA_BF16(a4, ah[mt], bh[2 * t], bh[2 * t + 1]);
                    MMA_BF16(a4, ah[mt], bl[2 * t], bl[2 * t + 1]);
                    MMA_BF16(a4, al[mt], bh[2 * t], bh[2 * t + 1]);
                }
            }
        }
        __syncthreads();
    }

    const int lr = lane >> 2;
    const int lc = (lane & 3) * 2;
#pragma unroll
    for (int mt = 0; mt < 2; ++mt) {
#pragma unroll
        for (int g = 0; g < 8; ++g) {
            int col = wn * 64 + g * 8 + lc;
            float2 bv = *(const float2*)&bias[col];
#pragma unroll
            for (int half = 0; half < 2; ++half) {
                int r = bm + wm * 32 + mt * 16 + lr + half * 8;
                if (r >= M) continue;
                float z0 = acc[mt][g][2 * half + 0] + bv.x;
                float z1 = acc[mt][g][2 * half + 1] + bv.y;
                if (EPI == 1) { z0 = fmaxf(z0, 0.f); z1 = fmaxf(z1, 0.f); }
                if (EPI == 2) {
                    const float* rrow = A + (size_t)r * K_DIM;
                    float2 hx = *(const float2*)&rrow[col];
                    float2 ha = *(const float2*)&rrow[128 + col];
                    z0 = fmaxf(fmaxf(z0, 0.f) + hx.x + ha.x, 0.f);
                    z1 = fmaxf(fmaxf(z1, 0.f) + hx.y + ha.y, 0.f);
                }
                *(float2*)&C[(size_t)r * ldc + coff + col] = make_float2(z0, z1);
            }
        }
    }
}

// ---------------------------------------------------------------------------
// Classifier GEMM (R2 SIMT version).
__global__ __launch_bounds__(128)
void gemm_out(const float* __restrict__ A,
              const float* __restrict__ W,
              const float* __restrict__ bias,
              float* __restrict__ out, int M) {
    __shared__ float As[16][128];
    __shared__ float Ws[16 * 40];

    const int tid = threadIdx.x;
    const int bm  = blockIdx.x * 128;
    const int ty  = tid >> 3;
    const int tx  = tid & 7;
    const int rm  = ty * 8;
    const int cn  = tx * 5;

    float acc[8][5];
#pragma unroll
    for (int i = 0; i < 8; ++i)
#pragma unroll
        for (int j = 0; j < 5; ++j) acc[i][j] = 0.f;

    for (int k0 = 0; k0 < 128; k0 += 16) {
#pragma unroll
        for (int u0 = 0; u0 < 512; u0 += 128) {
            int u   = u0 + tid;
            int row = u >> 2;
            int kq  = (u & 3) * 4;
            int gr  = bm + row;
            float4 v = make_float4(0.f, 0.f, 0.f, 0.f);
            if (gr < M) v = *(const float4*)&A[(size_t)gr * 128 + k0 + kq];
            As[kq + 0][row] = v.x;
            As[kq + 1][row] = v.y;
            As[kq + 2][row] = v.z;
            As[kq + 3][row] = v.w;
        }
        for (int u = tid; u < 16 * 40; u += 128) {
            int kr = u / 40, cc = u % 40;
            Ws[u] = W[(size_t)(k0 + kr) * 40 + cc];
        }
        __syncthreads();

#pragma unroll
        for (int kk = 0; kk < 16; ++kk) {
            float4 a0 = *(const float4*)&As[kk][rm];
            float4 a1 = *(const float4*)&As[kk][rm + 4];
            float a[8] = {a0.x, a0.y, a0.z, a0.w, a1.x, a1.y, a1.z, a1.w};
            float w[5];
#pragma unroll
            for (int j = 0; j < 5; ++j) w[j] = Ws[kk * 40 + cn + j];
#pragma unroll
            for (int i = 0; i < 8; ++i)
#pragma unroll
                for (int j = 0; j < 5; ++j)
                    acc[i][j] = fmaf(a[i], w[j], acc[i][j]);
        }
        __syncthreads();
    }

    float bb[5];
#pragma unroll
    for (int j = 0; j < 5; ++j) bb[j] = bias[cn + j];
#pragma unroll
    for (int i = 0; i < 8; ++i) {
        int r = bm + rm + i;
        if (r >= M) break;
#pragma unroll
        for (int j = 0; j < 5; ++j)
            out[(size_t)r * 40 + cn + j] = acc[i][j] + bb[j];
    }
}

// ---------------------------------------------------------------------------
extern "C" void kernel_launch(void* const* d_in, const int* in_sizes, int n_in,
                              void* d_out, int out_size) {
    const float* x   = (const float*)d_in[0];
    const int*   ei  = (const int*)  d_in[1];
    const float* emb = (const float*)d_in[2];
    const float* wx1 = (const float*)d_in[3];
    const float* bx1 = (const float*)d_in[4];
    const float* wx2 = (const float*)d_in[5];
    const float* bx2 = (const float*)d_in[6];
    const float* wa1 = (const float*)d_in[7];
    const float* ba1 = (const float*)d_in[8];
    const float* wa2 = (const float*)d_in[9];
    const float* ba2 = (const float*)d_in[10];
    const float* ww1 = (const float*)d_in[11];
    const float* bw1 = (const float*)d_in[12];
    const float* wc  = (const float*)d_in[13];
    const float* bc  = (const float*)d_in[14];
    float* out = (float*)d_out;

    const int M = in_sizes[0] / INDIM;   // 100000
    const int E = in_sizes[1] / 2;       // 1600000

    float *agg, *deg, *hid, *hid2, *cat;
    __nv_bfloat16* wt;
    cudaGetSymbolAddress((void**)&agg,  g_agg);
    cudaGetSymbolAddress((void**)&deg,  g_deg);
    cudaGetSymbolAddress((void**)&hid,  g_hid);
    cudaGetSymbolAddress((void**)&hid2, g_hid2);
    cudaGetSymbolAddress((void**)&cat,  g_cat);
    cudaGetSymbolAddress((void**)&wt,   g_wt);

    __nv_bfloat16* WT1 = wt;
    __nv_bfloat16* WT2 = wt + 65536;
    __nv_bfloat16* WT3 = wt + 98304;
    __nv_bfloat16* WT4 = wt + 131072;
    __nv_bfloat16* WT5 = wt + 163840;

    // One-time side stream + fork/join events (created on the first,
    // non-captured correctness call; reused identically on every call).
    static cudaStream_t s_side = nullptr;
    static cudaEvent_t  ev_fork = nullptr, ev_join = nullptr;
    if (s_side == nullptr) {
        cudaStreamCreateWithFlags(&s_side, cudaStreamNonBlocking);
        cudaEventCreateWithFlags(&ev_fork, cudaEventDisableTiming);
        cudaEventCreateWithFlags(&ev_join, cudaEventDisableTiming);
    }

    const int n4 = M * (HID / 4);
    const int gb = (M + 127) / 128;   // 782

    // ---- fork: side stream handles the aggregation chain ----
    cudaEventRecord(ev_fork, 0);
    cudaStreamWaitEvent(s_side, ev_fork, 0);

    zero_kernel<<<(n4 + 255) / 256, 256, 0, s_side>>>((float4*)agg, deg, n4, M);
    scatter_kernel<<<(E + 7) / 8, 256, 0, s_side>>>(ei, emb, agg, deg, E);
    finalize_kernel<<<(n4 + 255) / 256, 256, 0, s_side>>>((float4*)agg, deg, M);
    cudaEventRecord(ev_join, s_side);

    // ---- main stream: weight prep + x-branch GEMMs (independent of agg) ----
    prep_all<<<(114688 + 255) / 256, 256>>>(wx1, wx2, wa1, wa2, ww1, wt);
    // G1: hid = relu(x @ wx1 + bx1)
    mma_gemm<INDIM, 1><<<gb, 256>>>(x, WT1, bx1, hid, 128, 0, M);
    // G2: cat[:,0:128] = hid @ wx2 + bx2
    mma_gemm<HID, 0><<<gb, 256>>>(hid, WT2, bx2, cat, 256, 0, M);

    // ---- join: everything below needs agg ----
    cudaStreamWaitEvent(0, ev_join, 0);

    // G3: hid2 = relu(agg @ wa1 + ba1)
    mma_gemm<HID, 1><<<gb, 256>>>(agg, WT3, ba1, hid2, 128, 0, M);
    // G4: cat[:,128:256] = hid2 @ wa2 + ba2
    mma_gemm<HID, 0><<<gb, 256>>>(hid2, WT4, ba2, cat, 256, 128, M);
    // G5: hid = relu(relu(cat @ ww1 + bw1) + hx + ha)
    mma_gemm<2 * HID, 2><<<gb, 256>>>(cat, WT5, bw1, hid, 128, 0, M);
    // G6: classifier
    gemm_out<<<gb, 128>>>(hid, wc, bc, out, M);
}

// round 7
// speedup vs baseline: 2.0782x; 1.1983x over previous
#include <cuda_runtime.h>
#include <cuda_bf16.h>
#include <math.h>
#include <stdint.h>

// ---------------------------------------------------------------------------
// LINKX forward. G1..G5 via mma.sync bf16 (2-term split). Edge aggregation
// via counting-sort binning + per-node gather (no fp32 atomics). Binning
// chain overlapped with x-branch GEMMs via side stream (capture fork/join).
// ---------------------------------------------------------------------------

#define NMAX   100000
#define EMAX   1600000
#define HID    128
#define INDIM  256

__device__ float g_agg[(size_t)NMAX * HID];
__device__ float g_hid[(size_t)NMAX * HID];
__device__ float g_hid2[(size_t)NMAX * HID];
__device__ float g_cat[(size_t)NMAX * 2 * HID];
__device__ __align__(16) __nv_bfloat16 g_wt[229376];
__device__ int g_cnt[NMAX];
__device__ int g_cur[NMAX];
__device__ int g_off[NMAX + 1];
__device__ int g_bins[EMAX];

// ---- tensor helpers -------------------------------------------------------
__device__ __forceinline__ uint32_t smem_u32(const void* p) {
    uint32_t a;
    asm("{ .reg .u64 t; cvta.to.shared.u64 t, %1; cvt.u32.u64 %0, t; }"
        : "=r"(a) : "l"(p));
    return a;
}

#define LDSM_X4(r0, r1, r2, r3, addr) \
    asm volatile("ldmatrix.sync.aligned.m8n8.x4.shared.b16 {%0,%1,%2,%3}, [%4];" \
                 : "=r"(r0), "=r"(r1), "=r"(r2), "=r"(r3) : "r"(addr))

#define MMA_BF16(acc, a, b0v, b1v) \
    asm volatile("mma.sync.aligned.m16n8k16.row.col.f32.bf16.bf16.f32 " \
                 "{%0,%1,%2,%3}, {%4,%5,%6,%7}, {%8,%9}, {%0,%1,%2,%3};" \
                 : "+f"((acc)[0]), "+f"((acc)[1]), "+f"((acc)[2]), "+f"((acc)[3]) \
                 : "r"((a)[0]), "r"((a)[1]), "r"((a)[2]), "r"((a)[3]), \
                   "r"(b0v), "r"(b1v))

__device__ __forceinline__ uint32_t pack_bf2(__nv_bfloat16 lo, __nv_bfloat16 hi) {
    __nv_bfloat162 p;
    p.x = lo; p.y = hi;
    return *reinterpret_cast<uint32_t*>(&p);
}

__device__ __forceinline__ void bsplit(float x, __nv_bfloat16& h, __nv_bfloat16& l) {
    h = __float2bfloat16(x);
    l = __float2bfloat16(x - __bfloat162float(h));
}

// ---------------------------------------------------------------------------
// Aggregation via binning (no fp atomics)
// ---------------------------------------------------------------------------
__global__ void zero_cnt(int* cnt, int* cur, int M) {
    int i = blockIdx.x * blockDim.x + threadIdx.x;
    if (i < M) { cnt[i] = 0; cur[i] = 0; }
}

__global__ void count_kernel(const int* __restrict__ ei, int* __restrict__ cnt, int E) {
    int i = blockIdx.x * blockDim.x + threadIdx.x;
    int stride = gridDim.x * blockDim.x;
    for (int e = i; e < E; e += stride)
        atomicAdd(&cnt[__ldg(&ei[E + e])], 1);
}

// One-block exclusive scan over M counts -> off[0..M]
__global__ void scan_kernel(const int* __restrict__ cnt, int* __restrict__ off, int M) {
    __shared__ int part[1024];
    const int t = threadIdx.x;
    const int chunk = (M + 1023) >> 10;
    const int beg = t * chunk;
    const int end = min(beg + chunk, M);
    int s = 0;
    for (int i = beg; i < end; ++i) s += cnt[i];
    part[t] = s;
    __syncthreads();
    for (int d = 1; d < 1024; d <<= 1) {
        int v = (t >= d) ? part[t - d] : 0;
        __syncthreads();
        part[t] += v;
        __syncthreads();
    }
    int run = (t == 0) ? 0 : part[t - 1];
    for (int i = beg; i < end; ++i) { off[i] = run; run += cnt[i]; }
    if (t == 1023) off[M] = run;
}

__global__ void fill_kernel(const int* __restrict__ ei,
                            const int* __restrict__ off,
                            int* __restrict__ cur,
                            int* __restrict__ bins, int E) {
    int i = blockIdx.x * blockDim.x + threadIdx.x;
    int stride = gridDim.x * blockDim.x;
    for (int e = i; e < E; e += stride) {
        int src = __ldg(&ei[e]);
        int dst = __ldg(&ei[E + e]);
        int slot = atomicAdd(&cur[dst], 1);
        bins[off[dst] + slot] = src;
    }
}

// One warp per node: mean of neighbor embedding rows (coalesced 512B reads).
__global__ void gather_kernel(const int* __restrict__ off,
                              const int* __restrict__ bins,
                              const float* __restrict__ emb,
                              float* __restrict__ agg, int M) {
    int w    = (blockIdx.x * blockDim.x + threadIdx.x) >> 5;
    int lane = threadIdx.x & 31;
    if (w >= M) return;
    int beg = __ldg(&off[w]);
    int end = __ldg(&off[w + 1]);
    float4 acc = make_float4(0.f, 0.f, 0.f, 0.f);
    int e = beg;
    // 2-deep software pipeline for MLP
    for (; e + 1 < end; e += 2) {
        int s0 = __ldg(&bins[e]);
        int s1 = __ldg(&bins[e + 1]);
        float4 v0 = __ldg((const float4*)(emb + (size_t)s0 * HID + lane * 4));
        float4 v1 = __ldg((const float4*)(emb + (size_t)s1 * HID + lane * 4));
        acc.x += v0.x + v1.x; acc.y += v0.y + v1.y;
        acc.z += v0.z + v1.z; acc.w += v0.w + v1.w;
    }
    if (e < end) {
        int s0 = __ldg(&bins[e]);
        float4 v0 = __ldg((const float4*)(emb + (size_t)s0 * HID + lane * 4));
        acc.x += v0.x; acc.y += v0.y; acc.z += v0.z; acc.w += v0.w;
    }
    float inv = 1.0f / (float)max(end - beg, 1);
    acc.x *= inv; acc.y *= inv; acc.z *= inv; acc.w *= inv;
    *(float4*)(agg + (size_t)w * HID + lane * 4) = acc;
}

// ---------------------------------------------------------------------------
// Merged weight prep (5 matrices, one launch). hi[128][K] | lo[128][K].
__global__ void prep_all(const float* __restrict__ wx1, const float* __restrict__ wx2,
                         const float* __restrict__ wa1, const float* __restrict__ wa2,
                         const float* __restrict__ ww1, __nv_bfloat16* __restrict__ WT) {
    int t = blockIdx.x * blockDim.x + threadIdx.x;
    const float* W;
    __nv_bfloat16* D;
    int K, base;
    if (t < 32768)      { W = wx1; D = WT;          K = 256; base = 0; }
    else if (t < 49152) { W = wx2; D = WT + 65536;  K = 128; base = 32768; }
    else if (t < 65536) { W = wa1; D = WT + 98304;  K = 128; base = 49152; }
    else if (t < 81920) { W = wa2; D = WT + 131072; K = 128; base = 65536; }
    else if (t < 114688){ W = ww1; D = WT + 163840; K = 256; base = 81920; }
    else return;
    int u = t - base;
    int k = u >> 7, n = u & 127;
    __nv_bfloat16 h, l;
    bsplit(W[u], h, l);
    D[(size_t)n * K + k] = h;
    D[(size_t)128 * K + (size_t)n * K + k] = l;
}

// ---------------------------------------------------------------------------
// bf16-split tensor GEMM (known good).
template <int K_DIM, int EPI>
__global__ __launch_bounds__(256, 2)
void mma_gemm(const float* __restrict__ A,
              const __nv_bfloat16* __restrict__ WT,
              const float* __restrict__ bias,
              float* __restrict__ C, int ldc, int coff, int M) {
    __shared__ __align__(16) __nv_bfloat16 AH[128 * 24];
    __shared__ __align__(16) __nv_bfloat16 AL[128 * 24];
    __shared__ __align__(16) __nv_bfloat16 BH[128 * 24];
    __shared__ __align__(16) __nv_bfloat16 BL[128 * 24];

    const int tid  = threadIdx.x;
    const int wid  = tid >> 5;
    const int lane = tid & 31;
    const int wm   = wid >> 1;
    const int wn   = wid & 1;
    const int bm   = blockIdx.x * 128;

    const uint32_t uAH = smem_u32(AH);
    const uint32_t uAL = smem_u32(AL);
    const uint32_t uBH = smem_u32(BH);
    const uint32_t uBL = smem_u32(BL);

    float acc[2][8][4];
#pragma unroll
    for (int i = 0; i < 2; ++i)
#pragma unroll
        for (int j = 0; j < 8; ++j)
#pragma unroll
            for (int q = 0; q < 4; ++q) acc[i][j][q] = 0.f;

    const int a_r0 = (lane & 7) + ((lane >> 3) & 1) * 8;
    const int a_ch = lane >> 4;
    const int b_n0 = (lane & 7) + ((lane >> 4) & 1) * 8;
    const int b_ch = (lane >> 3) & 1;

    const int NC = K_DIM / 16;
    for (int c = 0; c < NC; ++c) {
        const int k0 = c * 16;
        {
            int row = tid >> 1, h = tid & 1;
            int gr  = bm + row;
            float4 v0 = make_float4(0.f, 0.f, 0.f, 0.f), v1 = v0;
            if (gr < M) {
                const float* p = A + (size_t)gr * K_DIM + k0 + h * 8;
                v0 = *(const float4*)p;
                v1 = *(const float4*)(p + 4);
            }
            __nv_bfloat16 h0,h1,h2,h3,h4,h5,h6,h7, l0,l1,l2,l3,l4,l5,l6,l7;
            bsplit(v0.x, h0, l0); bsplit(v0.y, h1, l1);
            bsplit(v0.z, h2, l2); bsplit(v0.w, h3, l3);
            bsplit(v1.x, h4, l4); bsplit(v1.y, h5, l5);
            bsplit(v1.z, h6, l6); bsplit(v1.w, h7, l7);
            uint4 hv = make_uint4(pack_bf2(h0,h1), pack_bf2(h2,h3),
                                  pack_bf2(h4,h5), pack_bf2(h6,h7));
            uint4 lv = make_uint4(pack_bf2(l0,l1), pack_bf2(l2,l3),
                                  pack_bf2(l4,l5), pack_bf2(l6,l7));
            *(uint4*)&AH[row * 24 + h * 8] = hv;
            *(uint4*)&AL[row * 24 + h * 8] = lv;
        }
        {
            int n = tid >> 1, h = tid & 1;
            uint4 hv = *(const uint4*)&WT[(size_t)n * K_DIM + k0 + h * 8];
            uint4 lv = *(const uint4*)&WT[(size_t)128 * K_DIM + (size_t)n * K_DIM + k0 + h * 8];
            *(uint4*)&BH[n * 24 + h * 8] = hv;
            *(uint4*)&BL[n * 24 + h * 8] = lv;
        }
        __syncthreads();

        uint32_t ah[2][4], al[2][4];
#pragma unroll
        for (int mt = 0; mt < 2; ++mt) {
            int arow = wm * 32 + mt * 16 + a_r0;
            LDSM_X4(ah[mt][0], ah[mt][1], ah[mt][2], ah[mt][3],
                    uAH + arow * 48 + a_ch * 16);
            LDSM_X4(al[mt][0], al[mt][1], al[mt][2], al[mt][3],
                    uAL + arow * 48 + a_ch * 16);
        }
#pragma unroll
        for (int np = 0; np < 4; ++np) {
            int bn = wn * 64 + np * 16 + b_n0;
            uint32_t bh[4], bl[4];
            LDSM_X4(bh[0], bh[1], bh[2], bh[3], uBH + bn * 48 + b_ch * 16);
            LDSM_X4(bl[0], bl[1], bl[2], bl[3], uBL + bn * 48 + b_ch * 16);
#pragma unroll
            for (int mt = 0; mt < 2; ++mt) {
#pragma unroll
                for (int t = 0; t < 2; ++t) {
                    float* a4 = acc[mt][np * 2 + t];
                    MMA_BF16(a4, ah[mt], bh[2 * t], bh[2 * t + 1]);
                    MMA_BF16(a4, ah[mt], bl[2 * t], bl[2 * t + 1]);
                    MMA_BF16(a4, al[mt], bh[2 * t], bh[2 * t + 1]);
                }
            }
        }
        __syncthreads();
    }

    const int lr = lane >> 2;
    const int lc = (lane & 3) * 2;
#pragma unroll
    for (int mt = 0; mt < 2; ++mt) {
#pragma unroll
        for (int g = 0; g < 8; ++g) {
            int col = wn * 64 + g * 8 + lc;
            float2 bv = *(const float2*)&bias[col];
#pragma unroll
            for (int half = 0; half < 2; ++half) {
                int r = bm + wm * 32 + mt * 16 + lr + half * 8;
                if (r >= M) continue;
                float z0 = acc[mt][g][2 * half + 0] + bv.x;
                float z1 = acc[mt][g][2 * half + 1] + bv.y;
                if (EPI == 1) { z0 = fmaxf(z0, 0.f); z1 = fmaxf(z1, 0.f); }
                if (EPI == 2) {
                    const float* rrow = A + (size_t)r * K_DIM;
                    float2 hx = *(const float2*)&rrow[col];
                    float2 ha = *(const float2*)&rrow[128 + col];
                    z0 = fmaxf(fmaxf(z0, 0.f) + hx.x + ha.x, 0.f);
                    z1 = fmaxf(fmaxf(z1, 0.f) + hx.y + ha.y, 0.f);
                }
                *(float2*)&C[(size_t)r * ldc + coff + col] = make_float2(z0, z1);
            }
        }
    }
}

// ---------------------------------------------------------------------------
// Classifier GEMM (SIMT).
__global__ __launch_bounds__(128)
void gemm_out(const float* __restrict__ A,
              const float* __restrict__ W,
              const float* __restrict__ bias,
              float* __restrict__ out, int M) {
    __shared__ float As[16][128];
    __shared__ float Ws[16 * 40];

    const int tid = threadIdx.x;
    const int bm  = blockIdx.x * 128;
    const int ty  = tid >> 3;
    const int tx  = tid & 7;
    const int rm  = ty * 8;
    const int cn  = tx * 5;

    float acc[8][5];
#pragma unroll
    for (int i = 0; i < 8; ++i)
#pragma unroll
        for (int j = 0; j < 5; ++j) acc[i][j] = 0.f;

    for (int k0 = 0; k0 < 128; k0 += 16) {
#pragma unroll
        for (int u0 = 0; u0 < 512; u0 += 128) {
            int u   = u0 + tid;
            int row = u >> 2;
            int kq  = (u & 3) * 4;
            int gr  = bm + row;
            float4 v = make_float4(0.f, 0.f, 0.f, 0.f);
            if (gr < M) v = *(const float4*)&A[(size_t)gr * 128 + k0 + kq];
            As[kq + 0][row] = v.x;
            As[kq + 1][row] = v.y;
            As[kq + 2][row] = v.z;
            As[kq + 3][row] = v.w;
        }
        for (int u = tid; u < 16 * 40; u += 128) {
            int kr = u / 40, cc = u % 40;
            Ws[u] = W[(size_t)(k0 + kr) * 40 + cc];
        }
        __syncthreads();

#pragma unroll
        for (int kk = 0; kk < 16; ++kk) {
            float4 a0 = *(const float4*)&As[kk][rm];
            float4 a1 = *(const float4*)&As[kk][rm + 4];
            float a[8] = {a0.x, a0.y, a0.z, a0.w, a1.x, a1.y, a1.z, a1.w};
            float w[5];
#pragma unroll
            for (int j = 0; j < 5; ++j) w[j] = Ws[kk * 40 + cn + j];
#pragma unroll
            for (int i = 0; i < 8; ++i)
#pragma unroll
                for (int j = 0; j < 5; ++j)
                    acc[i][j] = fmaf(a[i], w[j], acc[i][j]);
        }
        __syncthreads();
    }

    float bb[5];
#pragma unroll
    for (int j = 0; j < 5; ++j) bb[j] = bias[cn + j];
#pragma unroll
    for (int i = 0; i < 8; ++i) {
        int r = bm + rm + i;
        if (r >= M) break;
#pragma unroll
        for (int j = 0; j < 5; ++j)
            out[(size_t)r * 40 + cn + j] = acc[i][j] + bb[j];
    }
}

// ---------------------------------------------------------------------------
extern "C" void kernel_launch(void* const* d_in, const int* in_sizes, int n_in,
                              void* d_out, int out_size) {
    const float* x   = (const float*)d_in[0];
    const int*   ei  = (const int*)  d_in[1];
    const float* emb = (const float*)d_in[2];
    const float* wx1 = (const float*)d_in[3];
    const float* bx1 = (const float*)d_in[4];
    const float* wx2 = (const float*)d_in[5];
    const float* bx2 = (const float*)d_in[6];
    const float* wa1 = (const float*)d_in[7];
    const float* ba1 = (const float*)d_in[8];
    const float* wa2 = (const float*)d_in[9];
    const float* ba2 = (const float*)d_in[10];
    const float* ww1 = (const float*)d_in[11];
    const float* bw1 = (const float*)d_in[12];
    const float* wc  = (const float*)d_in[13];
    const float* bc  = (const float*)d_in[14];
    float* out = (float*)d_out;

    const int M = in_sizes[0] / INDIM;   // 100000
    const int E = in_sizes[1] / 2;       // 1600000

    float *agg, *hid, *hid2, *cat;
    __nv_bfloat16* wt;
    int *cnt, *cur, *off, *bins;
    cudaGetSymbolAddress((void**)&agg,  g_agg);
    cudaGetSymbolAddress((void**)&hid,  g_hid);
    cudaGetSymbolAddress((void**)&hid2, g_hid2);
    cudaGetSymbolAddress((void**)&cat,  g_cat);
    cudaGetSymbolAddress((void**)&wt,   g_wt);
    cudaGetSymbolAddress((void**)&cnt,  g_cnt);
    cudaGetSymbolAddress((void**)&cur,  g_cur);
    cudaGetSymbolAddress((void**)&off,  g_off);
    cudaGetSymbolAddress((void**)&bins, g_bins);

    __nv_bfloat16* WT1 = wt;
    __nv_bfloat16* WT2 = wt + 65536;
    __nv_bfloat16* WT3 = wt + 98304;
    __nv_bfloat16* WT4 = wt + 131072;
    __nv_bfloat16* WT5 = wt + 163840;

    static cudaStream_t s_side = nullptr;
    static cudaEvent_t  ev_fork = nullptr, ev_join = nullptr;
    if (s_side == nullptr) {
        cudaStreamCreateWithFlags(&s_side, cudaStreamNonBlocking);
        cudaEventCreateWithFlags(&ev_fork, cudaEventDisableTiming);
        cudaEventCreateWithFlags(&ev_join, cudaEventDisableTiming);
    }

    const int gb = (M + 127) / 128;   // 782

    // ---- fork: side stream runs the aggregation chain (no fp atomics) ----
    cudaEventRecord(ev_fork, 0);
    cudaStreamWaitEvent(s_side, ev_fork, 0);

    zero_cnt<<<(M + 255) / 256, 256, 0, s_side>>>(cnt, cur, M);
    count_kernel<<<1184, 256, 0, s_side>>>(ei, cnt, E);
    scan_kernel<<<1, 1024, 0, s_side>>>(cnt, off, M);
    fill_kernel<<<1184, 256, 0, s_side>>>(ei, off, cur, bins, E);
    gather_kernel<<<(M * 32 + 255) / 256, 256, 0, s_side>>>(off, bins, emb, agg, M);
    cudaEventRecord(ev_join, s_side);

    // ---- main stream: weight prep + x-branch GEMMs ----
    prep_all<<<(114688 + 255) / 256, 256>>>(wx1, wx2, wa1, wa2, ww1, wt);
    // G1: hid = relu(x @ wx1 + bx1)
    mma_gemm<INDIM, 1><<<gb, 256>>>(x, WT1, bx1, hid, 128, 0, M);
    // G2: cat[:,0:128] = hid @ wx2 + bx2
    mma_gemm<HID, 0><<<gb, 256>>>(hid, WT2, bx2, cat, 256, 0, M);

    // ---- join ----
    cudaStreamWaitEvent(0, ev_join, 0);

    // G3: hid2 = relu(agg @ wa1 + ba1)
    mma_gemm<HID, 1><<<gb, 256>>>(agg, WT3, ba1, hid2, 128, 0, M);
    // G4: cat[:,128:256] = hid2 @ wa2 + ba2
    mma_gemm<HID, 0><<<gb, 256>>>(hid2, WT4, ba2, cat, 256, 128, M);
    // G5: hid = relu(relu(cat @ ww1 + bw1) + hx + ha)
    mma_gemm<2 * HID, 2><<<gb, 256>>>(cat, WT5, bw1, hid, 128, 0, M);
    // G6: classifier
    gemm_out<<<gb, 128>>>(hid, wc, bc, out, M);
}

// round 8
// speedup vs baseline: 2.0869x; 1.0042x over previous
#include <cuda_runtime.h>
#include <cuda_bf16.h>
#include <math.h>
#include <stdint.h>

// ---------------------------------------------------------------------------
// LINKX forward.
//  - Aggregation: counting-sort binning + warp-per-node gather (no fp atomics),
//    gather epilogue emits bf16-split agg planes directly.
//  - GEMMs G1..G5: mma.sync bf16 2-term split (hh+hl+lh) with ALL operands
//    pre-split in gmem; cp.async double-buffered staging.
//  - Producer epilogues emit bf16-split outputs for the next GEMM.
//  - Side stream (binning chain) overlaps main stream (prep + G1 + G2).
// ---------------------------------------------------------------------------

#define NMAX   100000
#define EMAX   1600000
#define HID    128
#define INDIM  256

// fp32 scratch
__device__ float g_hid[(size_t)NMAX * HID];        // G5 out -> G6 in
__device__ float g_cat[(size_t)NMAX * 2 * HID];    // fp32 residual (hx|ha)
// bf16-split activation planes (hi plane, then lo plane)
__device__ __align__(16) __nv_bfloat16 g_xs[2 * (size_t)NMAX * INDIM];
__device__ __align__(16) __nv_bfloat16 g_hb[2 * (size_t)NMAX * HID];
__device__ __align__(16) __nv_bfloat16 g_h2b[2 * (size_t)NMAX * HID];
__device__ __align__(16) __nv_bfloat16 g_aggb[2 * (size_t)NMAX * HID];
__device__ __align__(16) __nv_bfloat16 g_catb[2 * (size_t)NMAX * 2 * HID];
__device__ __align__(16) __nv_bfloat16 g_wt[229376];
// binning scratch
__device__ int g_cnt[NMAX];
__device__ int g_cur[NMAX];
__device__ int g_off[NMAX + 1];
__device__ int g_bins[EMAX];

// ---- helpers --------------------------------------------------------------
__device__ __forceinline__ uint32_t smem_u32(const void* p) {
    uint32_t a;
    asm("{ .reg .u64 t; cvta.to.shared.u64 t, %1; cvt.u32.u64 %0, t; }"
        : "=r"(a) : "l"(p));
    return a;
}

#define LDSM_X4(r0, r1, r2, r3, addr) \
    asm volatile("ldmatrix.sync.aligned.m8n8.x4.shared.b16 {%0,%1,%2,%3}, [%4];" \
                 : "=r"(r0), "=r"(r1), "=r"(r2), "=r"(r3) : "r"(addr))

#define MMA_BF16(acc, a, b0v, b1v) \
    asm volatile("mma.sync.aligned.m16n8k16.row.col.f32.bf16.bf16.f32 " \
                 "{%0,%1,%2,%3}, {%4,%5,%6,%7}, {%8,%9}, {%0,%1,%2,%3};" \
                 : "+f"((acc)[0]), "+f"((acc)[1]), "+f"((acc)[2]), "+f"((acc)[3]) \
                 : "r"((a)[0]), "r"((a)[1]), "r"((a)[2]), "r"((a)[3]), \
                   "r"(b0v), "r"(b1v))

#define CP_ASYNC16(smem, gmem) \
    asm volatile("cp.async.cg.shared.global [%0], [%1], 16;" \
                 :: "r"(smem), "l"(gmem))
#define CP_COMMIT() asm volatile("cp.async.commit_group;")
#define CP_WAIT1()  asm volatile("cp.async.wait_group 1;")
#define CP_WAIT0()  asm volatile("cp.async.wait_group 0;")

__device__ __forceinline__ uint32_t pack_bf2(__nv_bfloat16 lo, __nv_bfloat16 hi) {
    __nv_bfloat162 p;
    p.x = lo; p.y = hi;
    return *reinterpret_cast<uint32_t*>(&p);
}

__device__ __forceinline__ void bsplit(float x, __nv_bfloat16& h, __nv_bfloat16& l) {
    h = __float2bfloat16(x);
    l = __float2bfloat16(x - __bfloat162float(h));
}

// ---------------------------------------------------------------------------
// Aggregation via binning
// ---------------------------------------------------------------------------
__global__ void zero_cnt(int* cnt, int* cur, int M) {
    int i = blockIdx.x * blockDim.x + threadIdx.x;
    if (i < M) { cnt[i] = 0; cur[i] = 0; }
}

__global__ void count_kernel(const int* __restrict__ ei, int* __restrict__ cnt, int E) {
    int i = blockIdx.x * blockDim.x + threadIdx.x;
    int stride = gridDim.x * blockDim.x;
    for (int e = i; e < E; e += stride)
        atomicAdd(&cnt[__ldg(&ei[E + e])], 1);
}

__global__ void scan_kernel(const int* __restrict__ cnt, int* __restrict__ off, int M) {
    __shared__ int part[1024];
    const int t = threadIdx.x;
    const int chunk = (M + 1023) >> 10;
    const int beg = t * chunk;
    const int end = min(beg + chunk, M);
    int s = 0;
    for (int i = beg; i < end; ++i) s += cnt[i];
    part[t] = s;
    __syncthreads();
    for (int d = 1; d < 1024; d <<= 1) {
        int v = (t >= d) ? part[t - d] : 0;
        __syncthreads();
        part[t] += v;
        __syncthreads();
    }
    int run = (t == 0) ? 0 : part[t - 1];
    for (int i = beg; i < end; ++i) { off[i] = run; run += cnt[i]; }
    if (t == 1023) off[M] = run;
}

__global__ void fill_kernel(const int* __restrict__ ei,
                            const int* __restrict__ off,
                            int* __restrict__ cur,
                            int* __restrict__ bins, int E) {
    int i = blockIdx.x * blockDim.x + threadIdx.x;
    int stride = gridDim.x * blockDim.x;
    for (int e = i; e < E; e += stride) {
        int src = __ldg(&ei[e]);
        int dst = __ldg(&ei[E + e]);
        int slot = atomicAdd(&cur[dst], 1);
        bins[off[dst] + slot] = src;
    }
}

// Warp-per-node gather; writes bf16-split agg planes directly.
__global__ void gather_kernel(const int* __restrict__ off,
                              const int* __restrict__ bins,
                              const float* __restrict__ emb,
                              __nv_bfloat16* __restrict__ aggh,
                              __nv_bfloat16* __restrict__ aggl, int M) {
    int w    = (blockIdx.x * blockDim.x + threadIdx.x) >> 5;
    int lane = threadIdx.x & 31;
    if (w >= M) return;
    int beg = __ldg(&off[w]);
    int end = __ldg(&off[w + 1]);
    float4 acc = make_float4(0.f, 0.f, 0.f, 0.f);
    int e = beg;
    for (; e + 1 < end; e += 2) {
        int s0 = __ldg(&bins[e]);
        int s1 = __ldg(&bins[e + 1]);
        float4 v0 = __ldg((const float4*)(emb + (size_t)s0 * HID + lane * 4));
        float4 v1 = __ldg((const float4*)(emb + (size_t)s1 * HID + lane * 4));
        acc.x += v0.x + v1.x; acc.y += v0.y + v1.y;
        acc.z += v0.z + v1.z; acc.w += v0.w + v1.w;
    }
    if (e < end) {
        int s0 = __ldg(&bins[e]);
        float4 v0 = __ldg((const float4*)(emb + (size_t)s0 * HID + lane * 4));
        acc.x += v0.x; acc.y += v0.y; acc.z += v0.z; acc.w += v0.w;
    }
    float inv = 1.0f / (float)max(end - beg, 1);
    __nv_bfloat16 h0,h1,h2,h3, l0,l1,l2,l3;
    bsplit(acc.x * inv, h0, l0);
    bsplit(acc.y * inv, h1, l1);
    bsplit(acc.z * inv, h2, l2);
    bsplit(acc.w * inv, h3, l3);
    size_t o = (size_t)w * HID + lane * 4;
    *(uint2*)(aggh + o) = make_uint2(pack_bf2(h0, h1), pack_bf2(h2, h3));
    *(uint2*)(aggl + o) = make_uint2(pack_bf2(l0, l1), pack_bf2(l2, l3));
}

// ---------------------------------------------------------------------------
// x -> bf16 split planes
__global__ void prep_x(const float4* __restrict__ x4,
                       __nv_bfloat16* __restrict__ xh,
                       __nv_bfloat16* __restrict__ xl, int n4) {
    int t = blockIdx.x * blockDim.x + threadIdx.x;
    if (t >= n4) return;
    float4 v = __ldg(&x4[t]);
    __nv_bfloat16 h0,h1,h2,h3, l0,l1,l2,l3;
    bsplit(v.x, h0, l0); bsplit(v.y, h1, l1);
    bsplit(v.z, h2, l2); bsplit(v.w, h3, l3);
    ((uint2*)xh)[t] = make_uint2(pack_bf2(h0, h1), pack_bf2(h2, h3));
    ((uint2*)xl)[t] = make_uint2(pack_bf2(l0, l1), pack_bf2(l2, l3));
}

// Merged weight prep (5 matrices). Each segment: hi[128][K] | lo[128][K].
__global__ void prep_all(const float* __restrict__ wx1, const float* __restrict__ wx2,
                         const float* __restrict__ wa1, const float* __restrict__ wa2,
                         const float* __restrict__ ww1, __nv_bfloat16* __restrict__ WT) {
    int t = blockIdx.x * blockDim.x + threadIdx.x;
    const float* W;
    __nv_bfloat16* D;
    int K, base;
    if (t < 32768)      { W = wx1; D = WT;          K = 256; base = 0; }
    else if (t < 49152) { W = wx2; D = WT + 65536;  K = 128; base = 32768; }
    else if (t < 65536) { W = wa1; D = WT + 98304;  K = 128; base = 49152; }
    else if (t < 81920) { W = wa2; D = WT + 131072; K = 128; base = 65536; }
    else if (t < 114688){ W = ww1; D = WT + 163840; K = 256; base = 81920; }
    else return;
    int u = t - base;
    int k = u >> 7, n = u & 127;
    __nv_bfloat16 h, l;
    bsplit(W[u], h, l);
    D[(size_t)n * K + k] = h;
    D[(size_t)128 * K + (size_t)n * K + k] = l;
}

// ---------------------------------------------------------------------------
// cp.async double-buffered bf16-split MMA GEMM.
// All operands pre-split bf16; C tile 128x128; 8 warps (wm 0..3, wn 0..1).
// RELU: relu before store. WBF: write bf16-split output. WF32: write fp32.
// COMBINE: z = relu(relu(z)+hx+ha) with hx/ha from res (fp32 cat, ld 256).
// ---------------------------------------------------------------------------
template <int K_DIM, int RELU, int WBF, int WF32, int COMBINE>
__global__ __launch_bounds__(256, 2)
void mma_gemm2(const __nv_bfloat16* __restrict__ Ah,
               const __nv_bfloat16* __restrict__ Al,
               const __nv_bfloat16* __restrict__ Bh,
               const __nv_bfloat16* __restrict__ Bl,
               const float* __restrict__ bias,
               __nv_bfloat16* __restrict__ Cbh,
               __nv_bfloat16* __restrict__ Cbl, int ldcb,
               float* __restrict__ Cf,
               const float* __restrict__ res,
               int ldc, int coff, int M) {
    // [stage][buf: AH AL BH BL][128*24]
    __shared__ __align__(16) __nv_bfloat16 S[2][4][128 * 24];

    const int tid  = threadIdx.x;
    const int wid  = tid >> 5;
    const int lane = tid & 31;
    const int wm   = wid >> 1;
    const int wn   = wid & 1;
    const int bm   = blockIdx.x * 128;

    const uint32_t uS = smem_u32(S);
    const int srow = tid >> 1;          // 0..127
    const int sh   = tid & 1;           // 16B half of 32B row-chunk
    const int gr   = min(bm + srow, M - 1);   // clamp (invalid rows never stored)

    const __nv_bfloat16* pAh = Ah + (size_t)gr * K_DIM + sh * 8;
    const __nv_bfloat16* pAl = Al + (size_t)gr * K_DIM + sh * 8;
    const __nv_bfloat16* pBh = Bh + (size_t)srow * K_DIM + sh * 8;
    const __nv_bfloat16* pBl = Bl + (size_t)srow * K_DIM + sh * 8;
    const uint32_t sdst = uS + srow * 48 + sh * 16;

#define ISSUE_STAGE(c, s) do {                                   \
        int _k0 = (c) * 16;                                      \
        uint32_t _b = sdst + (s) * 24576;                        \
        CP_ASYNC16(_b,          pAh + _k0);                      \
        CP_ASYNC16(_b + 6144,   pAl + _k0);                      \
        CP_ASYNC16(_b + 12288,  pBh + _k0);                      \
        CP_ASYNC16(_b + 18432,  pBl + _k0);                      \
        CP_COMMIT();                                             \
    } while (0)

    float acc[2][8][4];
#pragma unroll
    for (int i = 0; i < 2; ++i)
#pragma unroll
        for (int j = 0; j < 8; ++j)
#pragma unroll
            for (int q = 0; q < 4; ++q) acc[i][j][q] = 0.f;

    const int a_r0 = (lane & 7) + ((lane >> 3) & 1) * 8;
    const int a_ch = lane >> 4;
    const int b_n0 = (lane & 7) + ((lane >> 4) & 1) * 8;
    const int b_ch = (lane >> 3) & 1;

    const int NC = K_DIM / 16;
    ISSUE_STAGE(0, 0);

    for (int c = 0; c < NC; ++c) {
        const int s = c & 1;
        if (c + 1 < NC) { ISSUE_STAGE(c + 1, (c + 1) & 1); CP_WAIT1(); }
        else            { CP_WAIT0(); }
        __syncthreads();

        const uint32_t base = uS + s * 24576;
        uint32_t ah[2][4], al[2][4];
#pragma unroll
        for (int mt = 0; mt < 2; ++mt) {
            int arow = wm * 32 + mt * 16 + a_r0;
            LDSM_X4(ah[mt][0], ah[mt][1], ah[mt][2], ah[mt][3],
                    base + arow * 48 + a_ch * 16);
            LDSM_X4(al[mt][0], al[mt][1], al[mt][2], al[mt][3],
                    base + 6144 + arow * 48 + a_ch * 16);
        }
#pragma unroll
        for (int np = 0; np < 4; ++np) {
            int bn = wn * 64 + np * 16 + b_n0;
            uint32_t bh[4], bl[4];
            LDSM_X4(bh[0], bh[1], bh[2], bh[3],
                    base + 12288 + bn * 48 + b_ch * 16);
            LDSM_X4(bl[0], bl[1], bl[2], bl[3],
                    base + 18432 + bn * 48 + b_ch * 16);
#pragma unroll
            for (int mt = 0; mt < 2; ++mt) {
#pragma unroll
                for (int t = 0; t < 2; ++t) {
                    float* a4 = acc[mt][np * 2 + t];
                    MMA_BF16(a4, ah[mt], bh[2 * t], bh[2 * t + 1]);
                    MMA_BF16(a4, ah[mt], bl[2 * t], bl[2 * t + 1]);
                    MMA_BF16(a4, al[mt], bh[2 * t], bh[2 * t + 1]);
                }
            }
        }
        __syncthreads();
    }
#undef ISSUE_STAGE

    // ---- epilogue ----
    const int lr = lane >> 2;
    const int lc = (lane & 3) * 2;
#pragma unroll
    for (int mt = 0; mt < 2; ++mt) {
#pragma unroll
        for (int g = 0; g < 8; ++g) {
            int col = wn * 64 + g * 8 + lc;
            float2 bv = *(const float2*)&bias[col];
#pragma unroll
            for (int half = 0; half < 2; ++half) {
                int r = bm + wm * 32 + mt * 16 + lr + half * 8;
                if (r >= M) continue;
                float z0 = acc[mt][g][2 * half + 0] + bv.x;
                float z1 = acc[mt][g][2 * half + 1] + bv.y;
                if (RELU) { z0 = fmaxf(z0, 0.f); z1 = fmaxf(z1, 0.f); }
                if (COMBINE) {
                    const float* rrow = res + (size_t)r * 256;
                    float2 hx = *(const float2*)&rrow[col];
                    float2 ha = *(const float2*)&rrow[128 + col];
                    z0 = fmaxf(fmaxf(z0, 0.f) + hx.x + ha.x, 0.f);
                    z1 = fmaxf(fmaxf(z1, 0.f) + hx.y + ha.y, 0.f);
                }
                if (WF32)
                    *(float2*)&Cf[(size_t)r * ldc + coff + col] = make_float2(z0, z1);
                if (WBF) {
                    __nv_bfloat16 h0, l0, h1, l1;
                    bsplit(z0, h0, l0);
                    bsplit(z1, h1, l1);
                    size_t o = (size_t)r * ldcb + coff + col;
                    *(uint32_t*)(Cbh + o) = pack_bf2(h0, h1);
                    *(uint32_t*)(Cbl + o) = pack_bf2(l0, l1);
                }
            }
        }
    }
}

// ---------------------------------------------------------------------------
// Classifier GEMM (SIMT, fp32): out[M,40] = hid @ wc + bc
__global__ __launch_bounds__(128)
void gemm_out(const float* __restrict__ A,
              const float* __restrict__ W,
              const float* __restrict__ bias,
              float* __restrict__ out, int M) {
    __shared__ float As[16][128];
    __shared__ float Ws[16 * 40];

    const int tid = threadIdx.x;
    const int bm  = blockIdx.x * 128;
    const int ty  = tid >> 3;
    const int tx  = tid & 7;
    const int rm  = ty * 8;
    const int cn  = tx * 5;

    float acc[8][5];
#pragma unroll
    for (int i = 0; i < 8; ++i)
#pragma unroll
        for (int j = 0; j < 5; ++j) acc[i][j] = 0.f;

    for (int k0 = 0; k0 < 128; k0 += 16) {
#pragma unroll
        for (int u0 = 0; u0 < 512; u0 += 128) {
            int u   = u0 + tid;
            int row = u >> 2;
            int kq  = (u & 3) * 4;
            int grr = bm + row;
            float4 v = make_float4(0.f, 0.f, 0.f, 0.f);
            if (grr < M) v = *(const float4*)&A[(size_t)grr * 128 + k0 + kq];
            As[kq + 0][row] = v.x;
            As[kq + 1][row] = v.y;
            As[kq + 2][row] = v.z;
            As[kq + 3][row] = v.w;
        }
        for (int u = tid; u < 16 * 40; u += 128) {
            int kr = u / 40, cc = u % 40;
            Ws[u] = W[(size_t)(k0 + kr) * 40 + cc];
        }
        __syncthreads();

#pragma unroll
        for (int kk = 0; kk < 16; ++kk) {
            float4 a0 = *(const float4*)&As[kk][rm];
            float4 a1 = *(const float4*)&As[kk][rm + 4];
            float a[8] = {a0.x, a0.y, a0.z, a0.w, a1.x, a1.y, a1.z, a1.w};
            float w[5];
#pragma unroll
            for (int j = 0; j < 5; ++j) w[j] = Ws[kk * 40 + cn + j];
#pragma unroll
            for (int i = 0; i < 8; ++i)
#pragma unroll
                for (int j = 0; j < 5; ++j)
                    acc[i][j] = fmaf(a[i], w[j], acc[i][j]);
        }
        __syncthreads();
    }

    float bb[5];
#pragma unroll
    for (int j = 0; j < 5; ++j) bb[j] = bias[cn + j];
#pragma unroll
    for (int i = 0; i < 8; ++i) {
        int r = bm + rm + i;
        if (r >= M) break;
#pragma unroll
        for (int j = 0; j < 5; ++j)
            out[(size_t)r * 40 + cn + j] = acc[i][j] + bb[j];
    }
}

// ---------------------------------------------------------------------------
extern "C" void kernel_launch(void* const* d_in, const int* in_sizes, int n_in,
                              void* d_out, int out_size) {
    const float* x   = (const float*)d_in[0];
    const int*   ei  = (const int*)  d_in[1];
    const float* emb = (const float*)d_in[2];
    const float* wx1 = (const float*)d_in[3];
    const float* bx1 = (const float*)d_in[4];
    const float* wx2 = (const float*)d_in[5];
    const float* bx2 = (const float*)d_in[6];
    const float* wa1 = (const float*)d_in[7];
    const float* ba1 = (const float*)d_in[8];
    const float* wa2 = (const float*)d_in[9];
    const float* ba2 = (const float*)d_in[10];
    const float* ww1 = (const float*)d_in[11];
    const float* bw1 = (const float*)d_in[12];
    const float* wc  = (const float*)d_in[13];
    const float* bc  = (const float*)d_in[14];
    float* out = (float*)d_out;

    const int M = in_sizes[0] / INDIM;   // 100000
    const int E = in_sizes[1] / 2;       // 1600000

    float *hid, *cat;
    __nv_bfloat16 *wt, *xs, *hb, *h2b, *aggb, *catb;
    int *cnt, *cur, *off, *bins;
    cudaGetSymbolAddress((void**)&hid,  g_hid);
    cudaGetSymbolAddress((void**)&cat,  g_cat);
    cudaGetSymbolAddress((void**)&wt,   g_wt);
    cudaGetSymbolAddress((void**)&xs,   g_xs);
    cudaGetSymbolAddress((void**)&hb,   g_hb);
    cudaGetSymbolAddress((void**)&h2b,  g_h2b);
    cudaGetSymbolAddress((void**)&aggb, g_aggb);
    cudaGetSymbolAddress((void**)&catb, g_catb);
    cudaGetSymbolAddress((void**)&cnt,  g_cnt);
    cudaGetSymbolAddress((void**)&cur,  g_cur);
    cudaGetSymbolAddress((void**)&off,  g_off);
    cudaGetSymbolAddress((void**)&bins, g_bins);

    // plane pointers (hi, lo)
    __nv_bfloat16 *xsh = xs,   *xsl = xs   + (size_t)M * INDIM;
    __nv_bfloat16 *hbh = hb,   *hbl = hb   + (size_t)M * HID;
    __nv_bfloat16 *h2h = h2b,  *h2l = h2b  + (size_t)M * HID;
    __nv_bfloat16 *agh = aggb, *agl = aggb + (size_t)M * HID;
    __nv_bfloat16 *cbh = catb, *cbl = catb + (size_t)M * 2 * HID;
    // weight segments (hi plane at seg, lo plane at seg + 128*K)
    __nv_bfloat16 *W1h = wt,           *W1l = wt + 32768;    // wx1 K=256
    __nv_bfloat16 *W2h = wt + 65536,   *W2l = wt + 81920;    // wx2 K=128
    __nv_bfloat16 *W3h = wt + 98304,   *W3l = wt + 114688;   // wa1
    __nv_bfloat16 *W4h = wt + 131072,  *W4l = wt + 147456;   // wa2
    __nv_bfloat16 *W5h = wt + 163840,  *W5l = wt + 196608;   // ww1 K=256

    static cudaStream_t s_side = nullptr;
    static cudaEvent_t  ev_fork = nullptr, ev_join = nullptr;
    if (s_side == nullptr) {
        cudaStreamCreateWithFlags(&s_side, cudaStreamNonBlocking);
        cudaEventCreateWithFlags(&ev_fork, cudaEventDisableTiming);
        cudaEventCreateWithFlags(&ev_join, cudaEventDisableTiming);
    }

    const int gb = (M + 127) / 128;   // 782

    // ---- fork: side stream — binning + gather (emits bf16-split agg) ----
    cudaEventRecord(ev_fork, 0);
    cudaStreamWaitEvent(s_side, ev_fork, 0);

    zero_cnt<<<(M + 255) / 256, 256, 0, s_side>>>(cnt, cur, M);
    count_kernel<<<1184, 256, 0, s_side>>>(ei, cnt, E);
    scan_kernel<<<1, 1024, 0, s_side>>>(cnt, off, M);
    fill_kernel<<<1184, 256, 0, s_side>>>(ei, off, cur, bins, E);
    gather_kernel<<<(M * 32 + 255) / 256, 256, 0, s_side>>>(off, bins, emb, agh, agl, M);
    cudaEventRecord(ev_join, s_side);

    // ---- main stream: prep + x-branch ----
    prep_all<<<(114688 + 255) / 256, 256>>>(wx1, wx2, wa1, wa2, ww1, wt);
    const int n4x = M * (INDIM / 4);
    prep_x<<<(n4x + 255) / 256, 256>>>((const float4*)x, xsh, xsl, n4x);

    // G1: hb = relu(x @ wx1 + bx1)            [bf16-split out]
    mma_gemm2<INDIM, 1, 1, 0, 0><<<gb, 256>>>(xsh, xsl, W1h, W1l, bx1,
                                              hbh, hbl, HID, nullptr, nullptr, 0, 0, M);
    // G2: cat[:,0:128] = hb @ wx2 + bx2       [bf16-split + fp32 out]
    mma_gemm2<HID, 0, 1, 1, 0><<<gb, 256>>>(hbh, hbl, W2h, W2l, bx2,
                                            cbh, cbl, 256, cat, nullptr, 256, 0, M);

    // ---- join ----
    cudaStreamWaitEvent(0, ev_join, 0);

    // G3: h2b = relu(agg @ wa1 + ba1)         [bf16-split out]
    mma_gemm2<HID, 1, 1, 0, 0><<<gb, 256>>>(agh, agl, W3h, W3l, ba1,
                                            h2h, h2l, HID, nullptr, nullptr, 0, 0, M);
    // G4: cat[:,128:256] = h2b @ wa2 + ba2    [bf16-split + fp32 out]
    mma_gemm2<HID, 0, 1, 1, 0><<<gb, 256>>>(h2h, h2l, W4h, W4l, ba2,
                                            cbh, cbl, 256, cat, nullptr, 256, 128, M);
    // G5: hid = relu(relu(catb @ ww1 + bw1) + hx + ha)   [fp32 out]
    mma_gemm2<2 * HID, 0, 0, 1, 1><<<gb, 256>>>(cbh, cbl, W5h, W5l, bw1,
                                                nullptr, nullptr, 0, hid, cat, 128, 0, M);
    // G6: classifier
    gemm_out<<<gb, 128>>>(hid, wc, bc, out, M);
}